// round 1
// baseline (speedup 1.0000x reference)
#include <cuda_runtime.h>
#include <math.h>

// Problem constants
#define B_   2
#define S_   2048
#define D_   1024
#define H_   16
#define HD_  64
#define NTOK (B_ * S_)        // 4096
#define DFF  (4 * D_)         // 4096

// ---------------- scratch (static __device__, allocation-guard safe) ----------------
__device__ float g_xln[NTOK * D_];                       // 16 MB (reused for ln1 and ln2 outputs)
__device__ float g_q  [NTOK * D_];                       // 16 MB
__device__ float g_k  [NTOK * D_];                       // 16 MB
__device__ float g_v  [NTOK * D_];                       // 16 MB
__device__ float g_pre[NTOK * D_];                       // 16 MB  (attention pre-output, head-concat layout)
__device__ float g_x1 [NTOK * D_];                       // 16 MB  (x + attn)
__device__ float g_mid[NTOK * DFF];                      // 64 MB  (MLP hidden)
__device__ float g_scores[134217728];                    // 512 MB: B*H*S*S attention scores

// ---------------- generic tiled SGEMM ----------------
// C[M,N] = epilogue( alpha * A @ op(B) )
//   BT=true : op(B) = B^T with B stored [N,K] row-major  (the "x @ W.T" pattern)
//   BT=false: op(B) = B   with B stored [K,N] row-major  (the A @ V pattern)
// EPI: 0 = none, 1 = exact GELU, 2 = += residual R
// Batch (grid.z): z decomposed as (zo = z/zdiv, zi = z%zdiv); per-operand affine offsets.
// causal_mode: 1 = skip blocks entirely above the diagonal (logits), 2 = limit K to m0+BM (AV).
#define BM 128
#define BN 128
#define BK 8

template <bool BT, int EPI>
__global__ __launch_bounds__(256, 2)
void gemm_kernel(const float* __restrict__ A, const float* __restrict__ B,
                 float* __restrict__ C, const float* __restrict__ R,
                 int M, int N, int K,
                 int lda, int ldb, int ldc, int ldr,
                 int zdiv,
                 long long sAo, long long sAi,
                 long long sBo, long long sBi,
                 long long sCo, long long sCi,
                 float alpha, int causal_mode)
{
    const int bz = blockIdx.z;
    const int zo = bz / zdiv;
    const int zi = bz - zo * zdiv;
    A += zo * sAo + zi * sAi;
    B += zo * sBo + zi * sBi;
    C += zo * sCo + zi * sCi;

    const int m0 = blockIdx.y * BM;
    const int n0 = blockIdx.x * BN;

    if (causal_mode == 1 && n0 > m0 + (BM - 1)) return;   // fully-masked logits block
    int Kend = K;
    if (causal_mode == 2) Kend = min(K, m0 + BM);          // AV: attention rows are zero beyond q

    __shared__ float As[BK][BM + 4];
    __shared__ float Bs[BK][BN + 4];

    const int tid = threadIdx.x;
    const int tx = tid & 15;       // 0..15 -> 8 output cols each
    const int ty = tid >> 4;       // 0..15 -> 8 output rows each

    // A-tile loader: 128 rows x 8 k, float4 along k
    const int arow = tid >> 1;            // 0..127
    const int ak   = (tid & 1) << 2;      // 0 or 4
    // B-tile loader (NN): 8 k-rows x 128 n, float4 along n
    const int bkr = tid >> 5;             // 0..7
    const int bn  = (tid & 31) << 2;      // 0..124

    float acc[8][8];
    #pragma unroll
    for (int i = 0; i < 8; i++)
        #pragma unroll
        for (int j = 0; j < 8; j++) acc[i][j] = 0.f;

    for (int k0 = 0; k0 < Kend; k0 += BK) {
        // load A (M, K always multiples of 128 / 8 in this problem -> unguarded)
        float4 av = *reinterpret_cast<const float4*>(A + (long long)(m0 + arow) * lda + (k0 + ak));
        As[ak + 0][arow] = av.x;
        As[ak + 1][arow] = av.y;
        As[ak + 2][arow] = av.z;
        As[ak + 3][arow] = av.w;

        if (BT) {
            float4 bv = make_float4(0.f, 0.f, 0.f, 0.f);
            if (n0 + arow < N)
                bv = *reinterpret_cast<const float4*>(B + (long long)(n0 + arow) * ldb + (k0 + ak));
            Bs[ak + 0][arow] = bv.x;
            Bs[ak + 1][arow] = bv.y;
            Bs[ak + 2][arow] = bv.z;
            Bs[ak + 3][arow] = bv.w;
        } else {
            float4 bv = make_float4(0.f, 0.f, 0.f, 0.f);
            if (n0 + bn < N)
                bv = *reinterpret_cast<const float4*>(B + (long long)(k0 + bkr) * ldb + (n0 + bn));
            *reinterpret_cast<float4*>(&Bs[bkr][bn]) = bv;
        }
        __syncthreads();

        #pragma unroll
        for (int k = 0; k < BK; k++) {
            float ra[8], rb[8];
            *reinterpret_cast<float4*>(ra)     = *reinterpret_cast<const float4*>(&As[k][ty * 8]);
            *reinterpret_cast<float4*>(ra + 4) = *reinterpret_cast<const float4*>(&As[k][ty * 8 + 4]);
            *reinterpret_cast<float4*>(rb)     = *reinterpret_cast<const float4*>(&Bs[k][tx * 8]);
            *reinterpret_cast<float4*>(rb + 4) = *reinterpret_cast<const float4*>(&Bs[k][tx * 8 + 4]);
            #pragma unroll
            for (int i = 0; i < 8; i++)
                #pragma unroll
                for (int j = 0; j < 8; j++)
                    acc[i][j] = fmaf(ra[i], rb[j], acc[i][j]);
        }
        __syncthreads();
    }

    #pragma unroll
    for (int i = 0; i < 8; i++) {
        const int row = m0 + ty * 8 + i;
        #pragma unroll
        for (int j = 0; j < 8; j++) {
            const int col = n0 + tx * 8 + j;
            if (col < N) {
                float v = acc[i][j] * alpha;
                if (EPI == 1) v = 0.5f * v * (1.0f + erff(v * 0.70710678118654752f));
                if (EPI == 2) v += R[(long long)row * ldr + col];
                C[(long long)row * ldc + col] = v;
            }
        }
    }
}

// ---------------- LayerNorm (torch semantics: unbiased var, eps inside sqrt) ----------------
__global__ __launch_bounds__(256)
void ln_kernel(const float* __restrict__ x, float* __restrict__ y,
               const float* __restrict__ mean_scale, const float* __restrict__ std_scale)
{
    const int row = blockIdx.x;
    const float* xr = x + (long long)row * D_;
    float* yr = y + (long long)row * D_;
    const int tid = threadIdx.x;

    float s = 0.f, s2 = 0.f;
    for (int i = tid; i < D_; i += 256) {
        float v = xr[i];
        s += v;
        s2 += v * v;
    }
    #pragma unroll
    for (int o = 16; o > 0; o >>= 1) {
        s  += __shfl_down_sync(0xffffffffu, s, o);
        s2 += __shfl_down_sync(0xffffffffu, s2, o);
    }
    __shared__ float sh[8][2];
    const int w = tid >> 5, l = tid & 31;
    if (l == 0) { sh[w][0] = s; sh[w][1] = s2; }
    __syncthreads();
    if (tid == 0) {
        float S = 0.f, S2 = 0.f;
        #pragma unroll
        for (int i = 0; i < 8; i++) { S += sh[i][0]; S2 += sh[i][1]; }
        float mean = S * (1.0f / D_);
        float var  = (S2 - (float)D_ * mean * mean) * (1.0f / (D_ - 1));
        sh[0][0] = mean;
        sh[0][1] = rsqrtf(var + 1e-9f);
    }
    __syncthreads();
    const float mean = sh[0][0];
    const float rstd = sh[0][1];
    for (int i = tid; i < D_; i += 256)
        yr[i] = (xr[i] - mean) * rstd * std_scale[i] + mean_scale[i];
}

// ---------------- causal row softmax (in place), zeroing the masked tail ----------------
__global__ __launch_bounds__(128)
void softmax_kernel(float* __restrict__ scores)
{
    const long long row = blockIdx.x;              // 0 .. B*H*S-1
    const int q = (int)(row & (S_ - 1));
    float* p = scores + row * S_;
    const int L = q + 1;
    const int tid = threadIdx.x;
    const int w = tid >> 5, l = tid & 31;
    __shared__ float sh[4];

    float mx = -1e30f;
    for (int i = tid; i < L; i += 128) mx = fmaxf(mx, p[i]);
    #pragma unroll
    for (int o = 16; o > 0; o >>= 1) mx = fmaxf(mx, __shfl_xor_sync(0xffffffffu, mx, o));
    if (l == 0) sh[w] = mx;
    __syncthreads();
    mx = fmaxf(fmaxf(sh[0], sh[1]), fmaxf(sh[2], sh[3]));

    float sum = 0.f;
    for (int i = tid; i < L; i += 128) {
        float e = __expf(p[i] - mx);
        p[i] = e;
        sum += e;
    }
    #pragma unroll
    for (int o = 16; o > 0; o >>= 1) sum += __shfl_xor_sync(0xffffffffu, sum, o);
    __syncthreads();
    if (l == 0) sh[w] = sum;
    __syncthreads();
    sum = sh[0] + sh[1] + sh[2] + sh[3];

    const float inv = 1.0f / sum;
    for (int i = tid; i < L; i += 128) p[i] *= inv;
    for (int i = L + tid; i < S_; i += 128) p[i] = 0.f;   // masked tail -> AV reads zeros
}

// ---------------- launcher ----------------
extern "C" void kernel_launch(void* const* d_in, const int* in_sizes, int n_in,
                              void* d_out, int out_size)
{
    const float* x   = (const float*)d_in[0];
    const float* Wq  = (const float*)d_in[1];
    const float* Wk  = (const float*)d_in[2];
    const float* Wv  = (const float*)d_in[3];
    const float* Wo  = (const float*)d_in[4];
    const float* Wup = (const float*)d_in[5];
    const float* Wdn = (const float*)d_in[6];
    const float* m1  = (const float*)d_in[7];
    const float* s1  = (const float*)d_in[8];
    const float* m2  = (const float*)d_in[9];
    const float* s2  = (const float*)d_in[10];
    float* out = (float*)d_out;

    float *xln, *q, *k, *v, *pre, *x1, *mid, *sc;
    cudaGetSymbolAddress((void**)&xln, g_xln);
    cudaGetSymbolAddress((void**)&q,   g_q);
    cudaGetSymbolAddress((void**)&k,   g_k);
    cudaGetSymbolAddress((void**)&v,   g_v);
    cudaGetSymbolAddress((void**)&pre, g_pre);
    cudaGetSymbolAddress((void**)&x1,  g_x1);
    cudaGetSymbolAddress((void**)&mid, g_mid);
    cudaGetSymbolAddress((void**)&sc,  g_scores);

    const long long SD  = (long long)S_ * D_;    // per-batch token-block stride
    const long long SS  = (long long)S_ * S_;    // per-(b,h) score-matrix stride
    const dim3 blk(256);

    // 1) LN1
    ln_kernel<<<NTOK, 256>>>(x, xln, m1, s1);

    // 2-4) Q, K, V projections: [4096,1024] = xln @ W^T
    const dim3 gp(D_ / BN, NTOK / BM, 1);
    gemm_kernel<true, 0><<<gp, blk>>>(xln, Wq, q, nullptr, NTOK, D_, D_, D_, D_, D_, 0,
                                      1, 0, 0, 0, 0, 0, 0, 1.0f, 0);
    gemm_kernel<true, 0><<<gp, blk>>>(xln, Wk, k, nullptr, NTOK, D_, D_, D_, D_, D_, 0,
                                      1, 0, 0, 0, 0, 0, 0, 1.0f, 0);
    gemm_kernel<true, 0><<<gp, blk>>>(xln, Wv, v, nullptr, NTOK, D_, D_, D_, D_, D_, 0,
                                      1, 0, 0, 0, 0, 0, 0, 1.0f, 0);

    // 5) logits[b,h] = Q_bh @ K_bh^T / sqrt(64), skipping fully-masked upper blocks
    const dim3 gl(S_ / BN, S_ / BM, B_ * H_);
    gemm_kernel<true, 0><<<gl, blk>>>(q, k, sc, nullptr, S_, S_, HD_, D_, D_, S_, 0,
                                      H_, SD, HD_, SD, HD_, (long long)H_ * SS, SS,
                                      0.125f, 1);

    // 6) causal softmax rows
    softmax_kernel<<<B_ * H_ * S_, 128>>>(sc);

    // 7) preout[b,h] = A_bh @ V_bh  (NN, K limited causally)
    const dim3 ga(1, S_ / BM, B_ * H_);
    gemm_kernel<false, 0><<<ga, blk>>>(sc, v, pre, nullptr, S_, HD_, S_, S_, D_, D_, 0,
                                       H_, (long long)H_ * SS, SS, SD, HD_, SD, HD_,
                                       1.0f, 2);

    // 8) attn out + residual: x1 = x + pre @ Wo^T
    gemm_kernel<true, 2><<<gp, blk>>>(pre, Wo, x1, x, NTOK, D_, D_, D_, D_, D_, D_,
                                      1, 0, 0, 0, 0, 0, 0, 1.0f, 0);

    // 9) LN2
    ln_kernel<<<NTOK, 256>>>(x1, xln, m2, s2);

    // 10) MLP up + exact GELU: mid = gelu(xln @ Wup^T)
    const dim3 gu(DFF / BN, NTOK / BM, 1);
    gemm_kernel<true, 1><<<gu, blk>>>(xln, Wup, mid, nullptr, NTOK, DFF, D_, D_, D_, DFF, 0,
                                      1, 0, 0, 0, 0, 0, 0, 1.0f, 0);

    // 11) MLP down + residual into d_out: out = x1 + mid @ Wdn^T
    gemm_kernel<true, 2><<<gp, blk>>>(mid, Wdn, out, x1, NTOK, D_, DFF, DFF, DFF, D_, D_,
                                      1, 0, 0, 0, 0, 0, 0, 1.0f, 0);
}

// round 2
// speedup vs baseline: 2.5793x; 2.5793x over previous
#include <cuda_runtime.h>
#include <math.h>
#include <stdint.h>

// Problem constants
#define B_   2
#define S_   2048
#define D_   1024
#define H_   16
#define HD_  64
#define NTOK (B_ * S_)        // 4096
#define DFF  (4 * D_)         // 4096

// ---------------- scratch (static __device__, allocation-guard safe) ----------------
__device__ float g_xln[NTOK * D_];
__device__ float g_q  [NTOK * D_];
__device__ float g_k  [NTOK * D_];
__device__ float g_v  [NTOK * D_];
__device__ float g_pre[NTOK * D_];
__device__ float g_x1 [NTOK * D_];
__device__ float g_mid[NTOK * DFF];
__device__ float g_scores[134217728];   // 512 MB: B*H*S*S

// ---------------- tf32 tensor-core GEMM ----------------
// C[M,N] = epilogue( alpha * A @ op(B) )
//   BT=true : op(B)=B^T, B stored [N,K] row-major  (x @ W.T pattern; also Q@K^T)
//   BT=false: op(B)=B,   B stored [K,N] row-major  (probs @ V)
// EPI: 0 none, 1 exact GELU, 2 += residual R
// causal_mode: 1 = skip blocks above diagonal; 2 = Kend = min(K, m0+BM)
#define BM 128
#define BN 128
#define BK 16
#define PADA 20      // BK + 4  -> LDS bank-conflict-free for fragment loads
#define PADN 136     // BN + 8

__device__ __forceinline__ uint32_t f2tf32(float f) {
    uint32_t r;
    asm("cvt.rna.tf32.f32 %0, %1;" : "=r"(r) : "f"(f));
    return r;
}

__device__ __forceinline__ void mma_tf32(float* c,
                                         uint32_t a0, uint32_t a1, uint32_t a2, uint32_t a3,
                                         uint32_t b0, uint32_t b1) {
    asm volatile(
        "mma.sync.aligned.m16n8k8.row.col.f32.tf32.tf32.f32 "
        "{%0,%1,%2,%3},{%4,%5,%6,%7},{%8,%9},{%0,%1,%2,%3};"
        : "+f"(c[0]), "+f"(c[1]), "+f"(c[2]), "+f"(c[3])
        : "r"(a0), "r"(a1), "r"(a2), "r"(a3), "r"(b0), "r"(b1));
}

__device__ __forceinline__ void cp16(uint32_t smem_dst, const void* gsrc, int src_bytes) {
    asm volatile("cp.async.cg.shared.global [%0], [%1], 16, %2;"
                 :: "r"(smem_dst), "l"(gsrc), "r"(src_bytes));
}
__device__ __forceinline__ void cp_commit() { asm volatile("cp.async.commit_group;"); }
__device__ __forceinline__ void cp_wait0()  { asm volatile("cp.async.wait_group 0;"); }

template <bool BT, int EPI>
__global__ __launch_bounds__(256, 2)
void gemm_kernel(const float* __restrict__ A, const float* __restrict__ B,
                 float* __restrict__ C, const float* __restrict__ R,
                 int M, int N, int K,
                 int lda, int ldb, int ldc, int ldr,
                 int zdiv,
                 long long sAo, long long sAi,
                 long long sBo, long long sBi,
                 long long sCo, long long sCi,
                 float alpha, int causal_mode)
{
    const int bz = blockIdx.z;
    const int zo = bz / zdiv;
    const int zi = bz - zo * zdiv;
    A += zo * sAo + zi * sAi;
    B += zo * sBo + zi * sBi;
    C += zo * sCo + zi * sCi;

    const int m0 = blockIdx.y * BM;
    const int n0 = blockIdx.x * BN;

    if (causal_mode == 1 && n0 > m0 + (BM - 1)) return;
    int Kend = K;
    if (causal_mode == 2) Kend = min(K, m0 + BM);

    // As: [2][BM][PADA] raw fp32.  Bsh: BT -> [2][BN][PADA];  NN -> [2][BK][PADN]
    __shared__ float As[2][BM * PADA];
    __shared__ float Bsh[2][BM * PADA];   // 2560 floats per buf >= 16*136=2176

    const int tid  = threadIdx.x;
    const int lane = tid & 31;
    const int wid  = tid >> 5;
    const int g    = lane >> 2;       // groupID 0..7
    const int tg   = lane & 3;        // thread-in-group 0..3
    const int wm   = (wid & 1) * 64;  // warp row offset (2 warps along M)
    const int wn   = (wid >> 1) * 32; // warp col offset (4 warps along N)

    // loader indices
    const int rA = tid >> 1;                  // 0..127 row for A / BT-B (2 chunk-cols per thread)
    const int cA0 = (tid & 1) * 8;            // chunk float offset 0 or 8 (two 16B chunks each)
    const int krB = tid >> 5;                 // NN: k-row 0..7 (two rows: +8)
    const int cnB = (lane) * 4;               // NN: n float offset 0..124

    const float* Ag = A + (long long)m0 * lda;
    const float* Bg = BT ? (B + (long long)n0 * ldb) : (B + n0);

    const int nIt = Kend / BK;

    // ---- loaders (issue cp.async for buffer `b` at k-offset k0) ----
    auto loadA = [&](int b, int k0) {
        uint32_t dst = (uint32_t)__cvta_generic_to_shared(&As[b][rA * PADA + cA0]);
        const float* src = Ag + (long long)rA * lda + k0 + cA0;
        cp16(dst, src, 16);
        cp16(dst + 16, src + 4, 16);
    };
    auto loadB = [&](int b, int k0) {
        if (BT) {
            uint32_t dst = (uint32_t)__cvta_generic_to_shared(&Bsh[b][rA * PADA + cA0]);
            const float* src = Bg + (long long)rA * ldb + k0 + cA0;
            cp16(dst, src, 16);
            cp16(dst + 16, src + 4, 16);
        } else {
            // NN: Bsh[b][k][n] = B[k0+k][n0+n], guard n against N
            int ok = (n0 + cnB) < N ? 16 : 0;
            const float* s0 = Bg + (long long)(k0 + krB) * ldb + (ok ? cnB : 0);
            const float* s1 = Bg + (long long)(k0 + krB + 8) * ldb + (ok ? cnB : 0);
            cp16((uint32_t)__cvta_generic_to_shared(&Bsh[b][krB * PADN + cnB]), s0, ok);
            cp16((uint32_t)__cvta_generic_to_shared(&Bsh[b][(krB + 8) * PADN + cnB]), s1, ok);
        }
    };

    float acc[4][4][4];
    #pragma unroll
    for (int i = 0; i < 4; i++)
        #pragma unroll
        for (int j = 0; j < 4; j++)
            #pragma unroll
            for (int r = 0; r < 4; r++) acc[i][j][r] = 0.f;

    loadA(0, 0); loadB(0, 0); cp_commit();

    for (int it = 0; it < nIt; ++it) {
        cp_wait0();
        __syncthreads();
        const int buf = it & 1;
        if (it + 1 < nIt) { loadA(buf ^ 1, (it + 1) * BK); loadB(buf ^ 1, (it + 1) * BK); }
        cp_commit();

        const float* Asb = As[buf];
        const float* Bsb = Bsh[buf];

        #pragma unroll
        for (int ks = 0; ks < 2; ks++) {
            const int kk = ks * 8 + tg;
            uint32_t af[4][4];
            #pragma unroll
            for (int mt = 0; mt < 4; mt++) {
                const int r = wm + mt * 16 + g;
                af[mt][0] = f2tf32(Asb[r * PADA + kk]);
                af[mt][1] = f2tf32(Asb[(r + 8) * PADA + kk]);
                af[mt][2] = f2tf32(Asb[r * PADA + kk + 4]);
                af[mt][3] = f2tf32(Asb[(r + 8) * PADA + kk + 4]);
            }
            uint32_t bf[4][2];
            #pragma unroll
            for (int nt = 0; nt < 4; nt++) {
                const int n = wn + nt * 8 + g;
                if (BT) {
                    bf[nt][0] = f2tf32(Bsb[n * PADA + kk]);
                    bf[nt][1] = f2tf32(Bsb[n * PADA + kk + 4]);
                } else {
                    bf[nt][0] = f2tf32(Bsb[kk * PADN + n]);
                    bf[nt][1] = f2tf32(Bsb[(kk + 4) * PADN + n]);
                }
            }
            #pragma unroll
            for (int mt = 0; mt < 4; mt++)
                #pragma unroll
                for (int nt = 0; nt < 4; nt++)
                    mma_tf32(acc[mt][nt], af[mt][0], af[mt][1], af[mt][2], af[mt][3],
                             bf[nt][0], bf[nt][1]);
        }
    }

    // epilogue: c0=(g,2tg) c1=(g,2tg+1) c2=(g+8,2tg) c3=(g+8,2tg+1)
    #pragma unroll
    for (int mt = 0; mt < 4; mt++) {
        #pragma unroll
        for (int nt = 0; nt < 4; nt++) {
            const int r0 = m0 + wm + mt * 16 + g;
            const int c0 = n0 + wn + nt * 8 + 2 * tg;
            #pragma unroll
            for (int h = 0; h < 2; h++) {
                const int row = r0 + 8 * h;
                #pragma unroll
                for (int j = 0; j < 2; j++) {
                    const int col = c0 + j;
                    if (col < N) {
                        float v = acc[mt][nt][2 * h + j] * alpha;
                        if (EPI == 1) v = 0.5f * v * (1.0f + erff(v * 0.70710678118654752f));
                        if (EPI == 2) v += R[(long long)row * ldr + col];
                        C[(long long)row * ldc + col] = v;
                    }
                }
            }
        }
    }
}

// ---------------- LayerNorm (torch semantics: unbiased var, eps inside sqrt) ----------------
__global__ __launch_bounds__(256)
void ln_kernel(const float* __restrict__ x, float* __restrict__ y,
               const float* __restrict__ mean_scale, const float* __restrict__ std_scale)
{
    const int row = blockIdx.x;
    const float* xr = x + (long long)row * D_;
    float* yr = y + (long long)row * D_;
    const int tid = threadIdx.x;

    float s = 0.f, s2 = 0.f;
    for (int i = tid; i < D_; i += 256) {
        float v = xr[i];
        s += v;
        s2 += v * v;
    }
    #pragma unroll
    for (int o = 16; o > 0; o >>= 1) {
        s  += __shfl_down_sync(0xffffffffu, s, o);
        s2 += __shfl_down_sync(0xffffffffu, s2, o);
    }
    __shared__ float sh[8][2];
    const int w = tid >> 5, l = tid & 31;
    if (l == 0) { sh[w][0] = s; sh[w][1] = s2; }
    __syncthreads();
    if (tid == 0) {
        float S = 0.f, S2 = 0.f;
        #pragma unroll
        for (int i = 0; i < 8; i++) { S += sh[i][0]; S2 += sh[i][1]; }
        float mean = S * (1.0f / D_);
        float var  = (S2 - (float)D_ * mean * mean) * (1.0f / (D_ - 1));
        sh[0][0] = mean;
        sh[0][1] = rsqrtf(var + 1e-9f);
    }
    __syncthreads();
    const float mean = sh[0][0];
    const float rstd = sh[0][1];
    for (int i = tid; i < D_; i += 256)
        yr[i] = (xr[i] - mean) * rstd * std_scale[i] + mean_scale[i];
}

// ---------------- causal row softmax (in place), zeroing the masked tail ----------------
__global__ __launch_bounds__(128)
void softmax_kernel(float* __restrict__ scores)
{
    const long long row = blockIdx.x;
    const int q = (int)(row & (S_ - 1));
    float* p = scores + row * S_;
    const int L = q + 1;
    const int tid = threadIdx.x;
    const int w = tid >> 5, l = tid & 31;
    __shared__ float sh[4];

    float mx = -1e30f;
    for (int i = tid; i < L; i += 128) mx = fmaxf(mx, p[i]);
    #pragma unroll
    for (int o = 16; o > 0; o >>= 1) mx = fmaxf(mx, __shfl_xor_sync(0xffffffffu, mx, o));
    if (l == 0) sh[w] = mx;
    __syncthreads();
    mx = fmaxf(fmaxf(sh[0], sh[1]), fmaxf(sh[2], sh[3]));

    float sum = 0.f;
    for (int i = tid; i < L; i += 128) {
        float e = __expf(p[i] - mx);
        p[i] = e;
        sum += e;
    }
    #pragma unroll
    for (int o = 16; o > 0; o >>= 1) sum += __shfl_xor_sync(0xffffffffu, sum, o);
    __syncthreads();
    if (l == 0) sh[w] = sum;
    __syncthreads();
    sum = sh[0] + sh[1] + sh[2] + sh[3];

    const float inv = 1.0f / sum;
    for (int i = tid; i < L; i += 128) p[i] *= inv;
    for (int i = L + tid; i < S_; i += 128) p[i] = 0.f;
}

// ---------------- launcher ----------------
extern "C" void kernel_launch(void* const* d_in, const int* in_sizes, int n_in,
                              void* d_out, int out_size)
{
    const float* x   = (const float*)d_in[0];
    const float* Wq  = (const float*)d_in[1];
    const float* Wk  = (const float*)d_in[2];
    const float* Wv  = (const float*)d_in[3];
    const float* Wo  = (const float*)d_in[4];
    const float* Wup = (const float*)d_in[5];
    const float* Wdn = (const float*)d_in[6];
    const float* m1  = (const float*)d_in[7];
    const float* s1  = (const float*)d_in[8];
    const float* m2  = (const float*)d_in[9];
    const float* s2  = (const float*)d_in[10];
    float* out = (float*)d_out;

    float *xln, *q, *k, *v, *pre, *x1, *mid, *sc;
    cudaGetSymbolAddress((void**)&xln, g_xln);
    cudaGetSymbolAddress((void**)&q,   g_q);
    cudaGetSymbolAddress((void**)&k,   g_k);
    cudaGetSymbolAddress((void**)&v,   g_v);
    cudaGetSymbolAddress((void**)&pre, g_pre);
    cudaGetSymbolAddress((void**)&x1,  g_x1);
    cudaGetSymbolAddress((void**)&mid, g_mid);
    cudaGetSymbolAddress((void**)&sc,  g_scores);

    const long long SD = (long long)S_ * D_;
    const long long SS = (long long)S_ * S_;
    const dim3 blk(256);

    // 1) LN1
    ln_kernel<<<NTOK, 256>>>(x, xln, m1, s1);

    // 2-4) Q, K, V projections
    const dim3 gp(D_ / BN, NTOK / BM, 1);
    gemm_kernel<true, 0><<<gp, blk>>>(xln, Wq, q, nullptr, NTOK, D_, D_, D_, D_, D_, 0,
                                      1, 0, 0, 0, 0, 0, 0, 1.0f, 0);
    gemm_kernel<true, 0><<<gp, blk>>>(xln, Wk, k, nullptr, NTOK, D_, D_, D_, D_, D_, 0,
                                      1, 0, 0, 0, 0, 0, 0, 1.0f, 0);
    gemm_kernel<true, 0><<<gp, blk>>>(xln, Wv, v, nullptr, NTOK, D_, D_, D_, D_, D_, 0,
                                      1, 0, 0, 0, 0, 0, 0, 1.0f, 0);

    // 5) logits = Q @ K^T / 8, skip fully-masked upper blocks
    const dim3 gl(S_ / BN, S_ / BM, B_ * H_);
    gemm_kernel<true, 0><<<gl, blk>>>(q, k, sc, nullptr, S_, S_, HD_, D_, D_, S_, 0,
                                      H_, SD, HD_, SD, HD_, (long long)H_ * SS, SS,
                                      0.125f, 1);

    // 6) causal softmax
    softmax_kernel<<<B_ * H_ * S_, 128>>>(sc);

    // 7) preout = A @ V (NN, causal K limit)
    const dim3 ga(1, S_ / BM, B_ * H_);
    gemm_kernel<false, 0><<<ga, blk>>>(sc, v, pre, nullptr, S_, HD_, S_, S_, D_, D_, 0,
                                       H_, (long long)H_ * SS, SS, SD, HD_, SD, HD_,
                                       1.0f, 2);

    // 8) x1 = x + pre @ Wo^T
    gemm_kernel<true, 2><<<gp, blk>>>(pre, Wo, x1, x, NTOK, D_, D_, D_, D_, D_, D_,
                                      1, 0, 0, 0, 0, 0, 0, 1.0f, 0);

    // 9) LN2
    ln_kernel<<<NTOK, 256>>>(x1, xln, m2, s2);

    // 10) mid = gelu(xln @ Wup^T)
    const dim3 gu(DFF / BN, NTOK / BM, 1);
    gemm_kernel<true, 1><<<gu, blk>>>(xln, Wup, mid, nullptr, NTOK, DFF, D_, D_, D_, DFF, 0,
                                      1, 0, 0, 0, 0, 0, 0, 1.0f, 0);

    // 11) out = x1 + mid @ Wdn^T
    gemm_kernel<true, 2><<<gp, blk>>>(mid, Wdn, out, x1, NTOK, D_, DFF, DFF, DFF, D_, D_,
                                      1, 0, 0, 0, 0, 0, 0, 1.0f, 0);
}

// round 4
// speedup vs baseline: 3.0991x; 1.2016x over previous
#include <cuda_runtime.h>
#include <math.h>
#include <stdint.h>

// Problem constants
#define B_   2
#define S_   2048
#define D_   1024
#define H_   16
#define HD_  64
#define NTOK (B_ * S_)        // 4096
#define DFF  (4 * D_)         // 4096

// ---------------- scratch (static __device__, allocation-guard safe) ----------------
__device__ float g_xln[NTOK * D_];
__device__ float g_qkv[NTOK * 3 * D_];      // 48 MB: q | k | v column-blocks, ld = 3072
__device__ float g_pre[NTOK * D_];
__device__ float g_x1 [NTOK * D_];
__device__ float g_mid[NTOK * DFF];
__device__ float g_w  [12 * 1024 * 1024];   // rounded weights: q,k,v,o (1M each), up (4M), dn (4M)
__device__ float g_scores[134217728];       // 512 MB: B*H*S*S

#define BM 128
#define BN 128
#define BK 16
#define PADA 20      // row stride (floats): conflict-free for cp.async STS and ldmatrix
#define PADN 136     // NN B tile row stride

__device__ __forceinline__ uint32_t f2tf32(float f) {
    uint32_t r;
    asm("cvt.rna.tf32.f32 %0, %1;" : "=r"(r) : "f"(f));
    return r;
}
__device__ __forceinline__ float round_tf32(float f) { return __uint_as_float(f2tf32(f)); }

__device__ __forceinline__ void mma_tf32(float* c,
                                         uint32_t a0, uint32_t a1, uint32_t a2, uint32_t a3,
                                         uint32_t b0, uint32_t b1) {
    asm volatile(
        "mma.sync.aligned.m16n8k8.row.col.f32.tf32.tf32.f32 "
        "{%0,%1,%2,%3},{%4,%5,%6,%7},{%8,%9},{%0,%1,%2,%3};"
        : "+f"(c[0]), "+f"(c[1]), "+f"(c[2]), "+f"(c[3])
        : "r"(a0), "r"(a1), "r"(a2), "r"(a3), "r"(b0), "r"(b1));
}

__device__ __forceinline__ void ldmx4(uint32_t* r, uint32_t addr) {
    asm volatile("ldmatrix.sync.aligned.m8n8.x4.shared.b16 {%0,%1,%2,%3}, [%4];"
                 : "=r"(r[0]), "=r"(r[1]), "=r"(r[2]), "=r"(r[3]) : "r"(addr));
}

__device__ __forceinline__ void cp16(uint32_t smem_dst, const void* gsrc, int src_bytes) {
    asm volatile("cp.async.cg.shared.global [%0], [%1], 16, %2;"
                 :: "r"(smem_dst), "l"(gsrc), "r"(src_bytes));
}
__device__ __forceinline__ void cp_commit() { asm volatile("cp.async.commit_group;"); }
__device__ __forceinline__ void cp_wait0()  { asm volatile("cp.async.wait_group 0;"); }

// C[M,N] = epilogue( alpha * A @ op(B) )
//   BT=true : op(B)=B^T, B stored [N,K] row-major;  BT=false: op(B)=B, [K,N] row-major
// EPI: 0 none, 1 exact GELU, 2 += residual R.  RND: round C to tf32 at store.
// causal_mode: 1 = skip blocks above diagonal; 2 = Kend = min(K, m0+BM)
template <bool BT, int EPI, bool RND>
__global__ __launch_bounds__(256, 2)
void gemm_kernel(const float* __restrict__ A, const float* __restrict__ B,
                 float* __restrict__ C, const float* __restrict__ R,
                 int M, int N, int K,
                 int lda, int ldb, int ldc, int ldr,
                 int zdiv,
                 long long sAo, long long sAi,
                 long long sBo, long long sBi,
                 long long sCo, long long sCi,
                 float alpha, int causal_mode)
{
    const int bz = blockIdx.z;
    const int zo = bz / zdiv;
    const int zi = bz - zo * zdiv;
    A += zo * sAo + zi * sAi;
    B += zo * sBo + zi * sBi;
    C += zo * sCo + zi * sCi;

    const int m0 = blockIdx.y * BM;
    const int n0 = blockIdx.x * BN;

    if (causal_mode == 1 && n0 > m0 + (BM - 1)) return;
    int Kend = K;
    if (causal_mode == 2) Kend = min(K, m0 + BM);

    __shared__ float As[2][BM * PADA];
    __shared__ float Bsh[2][BM * PADA];   // NN uses 16*PADN=2176 <= 2560

    const int tid  = threadIdx.x;
    const int lane = tid & 31;
    const int wid  = tid >> 5;
    const int g    = lane >> 2;
    const int tg   = lane & 3;
    const int wm   = (wid & 1) * 64;
    const int wn   = (wid >> 1) * 32;
    const int mi   = lane >> 3;       // ldmatrix sub-matrix id 0..3
    const int ri   = lane & 7;        // row within sub-matrix

    const int rA  = tid >> 1;
    const int cA0 = (tid & 1) * 8;
    const int krB = tid >> 5;
    const int cnB = lane * 4;

    const float* Ag = A + (long long)m0 * lda;
    const float* Bg = BT ? (B + (long long)n0 * ldb) : (B + n0);

    const int nIt = Kend / BK;

    auto loadA = [&](int b, int k0) {
        uint32_t dst = (uint32_t)__cvta_generic_to_shared(&As[b][rA * PADA + cA0]);
        const float* src = Ag + (long long)rA * lda + k0 + cA0;
        cp16(dst, src, 16);
        cp16(dst + 16, src + 4, 16);
    };
    auto loadB = [&](int b, int k0) {
        if (BT) {
            uint32_t dst = (uint32_t)__cvta_generic_to_shared(&Bsh[b][rA * PADA + cA0]);
            const float* src = Bg + (long long)rA * ldb + k0 + cA0;
            cp16(dst, src, 16);
            cp16(dst + 16, src + 4, 16);
        } else {
            int ok = (n0 + cnB) < N ? 16 : 0;
            const float* s0 = Bg + (long long)(k0 + krB) * ldb + (ok ? cnB : 0);
            const float* s1 = Bg + (long long)(k0 + krB + 8) * ldb + (ok ? cnB : 0);
            cp16((uint32_t)__cvta_generic_to_shared(&Bsh[b][krB * PADN + cnB]), s0, ok);
            cp16((uint32_t)__cvta_generic_to_shared(&Bsh[b][(krB + 8) * PADN + cnB]), s1, ok);
        }
    };

    float acc[4][4][4];
    #pragma unroll
    for (int i = 0; i < 4; i++)
        #pragma unroll
        for (int j = 0; j < 4; j++)
            #pragma unroll
            for (int r = 0; r < 4; r++) acc[i][j][r] = 0.f;

    loadA(0, 0); loadB(0, 0); cp_commit();

    for (int it = 0; it < nIt; ++it) {
        cp_wait0();
        __syncthreads();
        const int buf = it & 1;
        if (it + 1 < nIt) { loadA(buf ^ 1, (it + 1) * BK); loadB(buf ^ 1, (it + 1) * BK); }
        cp_commit();

        const float* Asb = As[buf];
        const float* Bsb = Bsh[buf];

        const uint32_t a_base = (uint32_t)__cvta_generic_to_shared(
            &Asb[(wm + ri + ((mi & 1) << 3)) * PADA + ((mi >> 1) << 2)]);
        const uint32_t b_base = (uint32_t)__cvta_generic_to_shared(
            &Bsb[(wn + ri + ((mi >> 1) << 3)) * PADA + ((mi & 1) << 2)]);

        #pragma unroll
        for (int ks = 0; ks < 2; ks++) {
            uint32_t af[4][4];
            #pragma unroll
            for (int mt = 0; mt < 4; mt++)
                ldmx4(af[mt], a_base + (uint32_t)((mt * 16 * PADA + ks * 8) * 4));

            uint32_t bf[4][2];
            if (BT) {
                #pragma unroll
                for (int ntp = 0; ntp < 2; ntp++) {
                    uint32_t t[4];
                    ldmx4(t, b_base + (uint32_t)((ntp * 16 * PADA + ks * 8) * 4));
                    bf[2 * ntp][0] = t[0]; bf[2 * ntp][1] = t[1];
                    bf[2 * ntp + 1][0] = t[2]; bf[2 * ntp + 1][1] = t[3];
                }
            } else {
                const int kk = ks * 8 + tg;
                #pragma unroll
                for (int nt = 0; nt < 4; nt++) {
                    const int n = wn + nt * 8 + g;
                    bf[nt][0] = __float_as_uint(Bsb[kk * PADN + n]);
                    bf[nt][1] = __float_as_uint(Bsb[(kk + 4) * PADN + n]);
                }
            }
            #pragma unroll
            for (int mt = 0; mt < 4; mt++)
                #pragma unroll
                for (int nt = 0; nt < 4; nt++)
                    mma_tf32(acc[mt][nt], af[mt][0], af[mt][1], af[mt][2], af[mt][3],
                             bf[nt][0], bf[nt][1]);
        }
    }

    #pragma unroll
    for (int mt = 0; mt < 4; mt++) {
        #pragma unroll
        for (int nt = 0; nt < 4; nt++) {
            const int r0 = m0 + wm + mt * 16 + g;
            const int c0 = n0 + wn + nt * 8 + 2 * tg;
            #pragma unroll
            for (int h = 0; h < 2; h++) {
                const int row = r0 + 8 * h;
                #pragma unroll
                for (int j = 0; j < 2; j++) {
                    const int col = c0 + j;
                    if (col < N) {
                        float v = acc[mt][nt][2 * h + j] * alpha;
                        if (EPI == 1) v = 0.5f * v * (1.0f + erff(v * 0.70710678118654752f));
                        if (EPI == 2) v += R[(long long)row * ldr + col];
                        if (RND) v = round_tf32(v);
                        C[(long long)row * ldc + col] = v;
                    }
                }
            }
        }
    }
}

// ---------------- weight rounding pre-pass ----------------
__global__ __launch_bounds__(256)
void round4_kernel(const float* __restrict__ src, float* __restrict__ dst, int n4)
{
    int i = blockIdx.x * blockDim.x + threadIdx.x;
    if (i < n4) {
        float4 v = reinterpret_cast<const float4*>(src)[i];
        v.x = round_tf32(v.x); v.y = round_tf32(v.y);
        v.z = round_tf32(v.z); v.w = round_tf32(v.w);
        reinterpret_cast<float4*>(dst)[i] = v;
    }
}

// ---------------- LayerNorm (unbiased var), output rounded to tf32 ----------------
__global__ __launch_bounds__(256)
void ln_kernel(const float* __restrict__ x, float* __restrict__ y,
               const float* __restrict__ mean_scale, const float* __restrict__ std_scale)
{
    const int row = blockIdx.x;
    const float* xr = x + (long long)row * D_;
    float* yr = y + (long long)row * D_;
    const int tid = threadIdx.x;

    float s = 0.f, s2 = 0.f;
    for (int i = tid; i < D_; i += 256) {
        float v = xr[i];
        s += v;
        s2 += v * v;
    }
    #pragma unroll
    for (int o = 16; o > 0; o >>= 1) {
        s  += __shfl_down_sync(0xffffffffu, s, o);
        s2 += __shfl_down_sync(0xffffffffu, s2, o);
    }
    __shared__ float sh[8][2];
    const int w = tid >> 5, l = tid & 31;
    if (l == 0) { sh[w][0] = s; sh[w][1] = s2; }
    __syncthreads();
    if (tid == 0) {
        float S = 0.f, S2 = 0.f;
        #pragma unroll
        for (int i = 0; i < 8; i++) { S += sh[i][0]; S2 += sh[i][1]; }
        float mean = S * (1.0f / D_);
        float var  = (S2 - (float)D_ * mean * mean) * (1.0f / (D_ - 1));
        sh[0][0] = mean;
        sh[0][1] = rsqrtf(var + 1e-9f);
    }
    __syncthreads();
    const float mean = sh[0][0];
    const float rstd = sh[0][1];
    for (int i = tid; i < D_; i += 256)
        yr[i] = round_tf32((xr[i] - mean) * rstd * std_scale[i] + mean_scale[i]);
}

// ---------------- causal row softmax (in place), probs rounded to tf32 ----------------
__global__ __launch_bounds__(128)
void softmax_kernel(float* __restrict__ scores)
{
    const long long row = blockIdx.x;
    const int q = (int)(row & (S_ - 1));
    float* p = scores + row * S_;
    const int L = q + 1;
    const int tid = threadIdx.x;
    const int w = tid >> 5, l = tid & 31;
    __shared__ float sh[4];

    float mx = -1e30f;
    for (int i = tid; i < L; i += 128) mx = fmaxf(mx, p[i]);
    #pragma unroll
    for (int o = 16; o > 0; o >>= 1) mx = fmaxf(mx, __shfl_xor_sync(0xffffffffu, mx, o));
    if (l == 0) sh[w] = mx;
    __syncthreads();
    mx = fmaxf(fmaxf(sh[0], sh[1]), fmaxf(sh[2], sh[3]));

    float sum = 0.f;
    for (int i = tid; i < L; i += 128) {
        float e = __expf(p[i] - mx);
        p[i] = e;
        sum += e;
    }
    #pragma unroll
    for (int o = 16; o > 0; o >>= 1) sum += __shfl_xor_sync(0xffffffffu, sum, o);
    __syncthreads();
    if (l == 0) sh[w] = sum;
    __syncthreads();
    sum = sh[0] + sh[1] + sh[2] + sh[3];

    const float inv = 1.0f / sum;
    for (int i = tid; i < L; i += 128) p[i] = round_tf32(p[i] * inv);
    for (int i = L + tid; i < S_; i += 128) p[i] = 0.f;
}

// ---------------- launcher ----------------
extern "C" void kernel_launch(void* const* d_in, const int* in_sizes, int n_in,
                              void* d_out, int out_size)
{
    const float* x   = (const float*)d_in[0];
    const float* Wq  = (const float*)d_in[1];
    const float* Wk  = (const float*)d_in[2];
    const float* Wv  = (const float*)d_in[3];
    const float* Wo  = (const float*)d_in[4];
    const float* Wup = (const float*)d_in[5];
    const float* Wdn = (const float*)d_in[6];
    const float* m1  = (const float*)d_in[7];
    const float* s1  = (const float*)d_in[8];
    const float* m2  = (const float*)d_in[9];
    const float* s2  = (const float*)d_in[10];
    float* out = (float*)d_out;

    float *xln, *qkv, *pre, *x1, *mid, *sc, *wbuf;
    cudaGetSymbolAddress((void**)&xln, g_xln);
    cudaGetSymbolAddress((void**)&qkv, g_qkv);
    cudaGetSymbolAddress((void**)&pre, g_pre);
    cudaGetSymbolAddress((void**)&x1,  g_x1);
    cudaGetSymbolAddress((void**)&mid, g_mid);
    cudaGetSymbolAddress((void**)&sc,  g_scores);
    cudaGetSymbolAddress((void**)&wbuf, g_w);

    float* wqkv = wbuf;                      // [3072, 1024] = wq | wk | wv stacked rows
    float* wo   = wbuf + 3 * 1024 * 1024;
    float* wu   = wbuf + 4 * 1024 * 1024;
    float* wd   = wbuf + 8 * 1024 * 1024;

    const float* q = qkv;
    const float* k = qkv + D_;
    const float* v = qkv + 2 * D_;
    const int ldqkv = 3 * D_;

    const long long SD3 = (long long)S_ * ldqkv;   // per-batch stride in qkv buffer
    const long long SS  = (long long)S_ * S_;
    const dim3 blk(256);

    // 0) round weights to tf32 once per call
    round4_kernel<<<1024, 256>>>(Wq, wqkv,                     262144);
    round4_kernel<<<1024, 256>>>(Wk, wqkv + 1 * 1024 * 1024,   262144);
    round4_kernel<<<1024, 256>>>(Wv, wqkv + 2 * 1024 * 1024,   262144);
    round4_kernel<<<1024, 256>>>(Wo, wo, 262144);
    round4_kernel<<<4096, 256>>>(Wup, wu, 1048576);
    round4_kernel<<<4096, 256>>>(Wdn, wd, 1048576);

    // 1) LN1 (rounded output)
    ln_kernel<<<NTOK, 256>>>(x, xln, m1, s1);

    // 2) fused QKV projection: [4096, 3072] = xln @ Wqkv^T (rounded)
    const dim3 gqkv(3 * D_ / BN, NTOK / BM, 1);
    gemm_kernel<true, 0, true><<<gqkv, blk>>>(xln, wqkv, (float*)qkv, nullptr,
                                              NTOK, 3 * D_, D_, D_, D_, ldqkv, 0,
                                              1, 0, 0, 0, 0, 0, 0, 1.0f, 0);

    // 3) logits = Q @ K^T / 8 (skip masked blocks)
    const dim3 gl(S_ / BN, S_ / BM, B_ * H_);
    gemm_kernel<true, 0, false><<<gl, blk>>>(q, k, sc, nullptr, S_, S_, HD_,
                                             ldqkv, ldqkv, S_, 0,
                                             H_, SD3, HD_, SD3, HD_,
                                             (long long)H_ * SS, SS,
                                             0.125f, 1);

    // 4) causal softmax (rounded probs)
    softmax_kernel<<<B_ * H_ * S_, 128>>>(sc);

    // 5) preout = A @ V (NN, causal K limit; rounded output)
    const dim3 ga(1, S_ / BM, B_ * H_);
    gemm_kernel<false, 0, true><<<ga, blk>>>(sc, v, pre, nullptr, S_, HD_, S_,
                                             S_, ldqkv, D_, 0,
                                             H_, (long long)H_ * SS, SS,
                                             SD3, HD_, (long long)S_ * D_, HD_,
                                             1.0f, 2);

    // 6) x1 = x + pre @ Wo^T (fp32)
    const dim3 gp(D_ / BN, NTOK / BM, 1);
    gemm_kernel<true, 2, false><<<gp, blk>>>(pre, wo, x1, x, NTOK, D_, D_, D_, D_, D_, D_,
                                             1, 0, 0, 0, 0, 0, 0, 1.0f, 0);

    // 7) LN2 (rounded output)
    ln_kernel<<<NTOK, 256>>>(x1, xln, m2, s2);

    // 8) mid = gelu(xln @ Wup^T) (rounded)
    const dim3 gu(DFF / BN, NTOK / BM, 1);
    gemm_kernel<true, 1, true><<<gu, blk>>>(xln, wu, mid, nullptr, NTOK, DFF, D_, D_, D_, DFF, 0,
                                            1, 0, 0, 0, 0, 0, 0, 1.0f, 0);

    // 9) out = x1 + mid @ Wdn^T (fp32)
    gemm_kernel<true, 2, false><<<gp, blk>>>(mid, wd, out, x1, NTOK, D_, DFF, DFF, DFF, D_, D_,
                                             1, 0, 0, 0, 0, 0, 0, 1.0f, 0);
}